// round 17
// baseline (speedup 1.0000x reference)
#include <cuda_runtime.h>
#include <cuda_fp16.h>
#include <math.h>
#include <float.h>

#define DE 256
#define MAXN 50000
#define MAXG 256
#define MAXE 800000

// ------------------------------------------------------------- scratch
static __device__ int   g_deg[MAXN];
static __device__ int   g_rowptr[MAXN + 1];
static __device__ int   g_cursor[MAXN + 1];
static __device__ int   g_col[MAXE];
static __device__ int   g_gcnt[MAXG];
static __device__ int   g_gptr[MAXG + 1];
static __device__ int   g_part[512];
static __device__ float g_pool[MAXG * 1024];
// fp16 activations
static __device__ __align__(16) unsigned short g_x16[(size_t)MAXN * 128];
static __device__ __align__(16) unsigned short g_agg16[(size_t)MAXN * 256];
static __device__ __align__(16) unsigned short g_tmp16[(size_t)MAXN * 256];
static __device__ __align__(16) unsigned short g_hc16[(size_t)MAXN * 1024];
// pre-converted weights, fp16, layout [n=256][K]
static __device__ __align__(16) unsigned short g_W1h[4][256 * 512];
static __device__ __align__(16) unsigned short g_W2h[4][256 * 256];

// ---------------------------------------------------------------- utilities
__global__ void k_zero(int N, int G) {
    int i = blockIdx.x * blockDim.x + threadIdx.x;
    if (i < N) g_deg[i] = 0;
    if (i < G) g_gcnt[i] = 0;
}
__device__ __forceinline__ int clampi(int v, int n) {
    return v < 0 ? 0 : (v >= n ? n - 1 : v);
}
__global__ void k_hist_edges(const int* __restrict__ ei, int E, int N) {
    int e = blockIdx.x * blockDim.x + threadIdx.x;
    if (e < E) atomicAdd(&g_deg[clampi(ei[E + e], N)], 1);
}
__global__ void k_hist_nodes(const int* __restrict__ batch, int N, int G) {
    int i = blockIdx.x * blockDim.x + threadIdx.x;
    if (i < N) atomicAdd(&g_gcnt[clampi(batch[i], G)], 1);
}

// convert x to fp16 (monotone rounding: commutes with scatter-max)
__global__ void k_x16(const float* __restrict__ x, int n) {
    int i = blockIdx.x * 256 + threadIdx.x;
    if (i < n) g_x16[i] = __half_as_ushort(__float2half_rn(x[i]));
}

// three-phase multi-block exclusive scan
__global__ void k_scan_blk(const int* __restrict__ in, int* __restrict__ out, int n) {
    __shared__ int ws[8], wsx[8];
    int i = blockIdx.x * 256 + threadIdx.x;
    int v = (i < n) ? in[i] : 0;
    int lane = threadIdx.x & 31, w = threadIdx.x >> 5;
    int inc = v;
#pragma unroll
    for (int o = 1; o < 32; o <<= 1) {
        int t = __shfl_up_sync(0xffffffffu, inc, o);
        if (lane >= o) inc += t;
    }
    if (lane == 31) ws[w] = inc;
    __syncthreads();
    if (threadIdx.x == 0) {
        int run = 0;
#pragma unroll
        for (int j = 0; j < 8; j++) { int t = ws[j]; wsx[j] = run; run += t; }
        g_part[blockIdx.x] = run;
    }
    __syncthreads();
    if (i < n) out[i] = inc - v + wsx[w];
}
__global__ void k_scan_top(int nb, int* outA, int* outB, int n) {
    __shared__ int ws[8], wsx[8];
    int tid = threadIdx.x;
    int v = (tid < nb) ? g_part[tid] : 0;
    int lane = tid & 31, w = tid >> 5;
    int inc = v;
#pragma unroll
    for (int o = 1; o < 32; o <<= 1) {
        int t = __shfl_up_sync(0xffffffffu, inc, o);
        if (lane >= o) inc += t;
    }
    if (lane == 31) ws[w] = inc;
    __syncthreads();
    if (tid == 0) {
        int run = 0;
#pragma unroll
        for (int j = 0; j < 8; j++) { int t = ws[j]; wsx[j] = run; run += t; }
        outA[n] = run; outB[n] = run;
    }
    __syncthreads();
    int excl = inc - v + wsx[w];
    __syncthreads();
    if (tid < nb) g_part[tid] = excl;
}
__global__ void k_scan_add(int* __restrict__ out, int* __restrict__ out2, int n) {
    int i = blockIdx.x * 256 + threadIdx.x;
    if (i < n) { int v = out[i] + g_part[blockIdx.x]; out[i] = v; out2[i] = v; }
}

__global__ void k_scan(const int* __restrict__ in, int* __restrict__ out,
                       int* __restrict__ out2, int n) {
    __shared__ int wsum[32];
    int tid = threadIdx.x;
    int chunk = (n + blockDim.x - 1) / blockDim.x;
    int s = tid * chunk, e = min(s + chunk, n);
    int local = 0;
    for (int i = s; i < e; i++) local += in[i];
    int lane = tid & 31, wid = tid >> 5;
    int v = local;
#pragma unroll
    for (int o = 1; o < 32; o <<= 1) {
        int t = __shfl_up_sync(0xffffffffu, v, o);
        if (lane >= o) v += t;
    }
    if (lane == 31) wsum[wid] = v;
    __syncthreads();
    if (wid == 0) {
        int nw = blockDim.x >> 5;
        int w = (lane < nw) ? wsum[lane] : 0;
#pragma unroll
        for (int o = 1; o < 32; o <<= 1) {
            int t = __shfl_up_sync(0xffffffffu, w, o);
            if (lane >= o) w += t;
        }
        wsum[lane] = w;
    }
    __syncthreads();
    int excl = v - local + (wid ? wsum[wid - 1] : 0);
    int run = excl;
    for (int i = s; i < e; i++) { out[i] = run; out2[i] = run; run += in[i]; }
    if (s < n && e == n) { out[n] = run; out2[n] = run; }
}

__global__ void k_scatter(const int* __restrict__ ei, int E, int N) {
    int e = blockIdx.x * blockDim.x + threadIdx.x;
    if (e < E) {
        int d = clampi(ei[E + e], N);
        int p = atomicAdd(&g_cursor[d], 1);
        if (p < MAXE) g_col[p] = clampi(ei[e], N);
    }
}

// --------------------------------------------------- fp16 aggregation (max)
__global__ void k_agg16(const unsigned short* __restrict__ h, int ldh, int din,
                        unsigned short* __restrict__ out, int ldo, int N) {
    int w = (blockIdx.x * blockDim.x + threadIdx.x) >> 5;
    int lane = threadIdx.x & 31;
    if (w >= N) return;
    int s = g_rowptr[w], e = g_rowptr[w + 1];
    const unsigned NEG = 0xFC00FC00u;           // half2(-inf,-inf)
    __half2 m0 = *(__half2*)&NEG, m1 = m0, m2 = m0, m3 = m0;
    if (din == 256) {
        int j = s;
        for (; j + 1 < e; j += 2) {
            const uint4* r0 = (const uint4*)(h + (size_t)g_col[j] * ldh);
            const uint4* r1 = (const uint4*)(h + (size_t)g_col[j + 1] * ldh);
            uint4 a = r0[lane], b = r1[lane];
            m0 = __hmax2(m0, __hmax2(*(__half2*)&a.x, *(__half2*)&b.x));
            m1 = __hmax2(m1, __hmax2(*(__half2*)&a.y, *(__half2*)&b.y));
            m2 = __hmax2(m2, __hmax2(*(__half2*)&a.z, *(__half2*)&b.z));
            m3 = __hmax2(m3, __hmax2(*(__half2*)&a.w, *(__half2*)&b.w));
        }
        if (j < e) {
            uint4 a = ((const uint4*)(h + (size_t)g_col[j] * ldh))[lane];
            m0 = __hmax2(m0, *(__half2*)&a.x);
            m1 = __hmax2(m1, *(__half2*)&a.y);
            m2 = __hmax2(m2, *(__half2*)&a.z);
            m3 = __hmax2(m3, *(__half2*)&a.w);
        }
        if (e == s) { unsigned z = 0; m0 = *(__half2*)&z; m1 = m0; m2 = m0; m3 = m0; }
        uint4 o;
        o.x = *(unsigned*)&m0; o.y = *(unsigned*)&m1;
        o.z = *(unsigned*)&m2; o.w = *(unsigned*)&m3;
        ((uint4*)(out + (size_t)w * ldo))[lane] = o;
    } else {   // din == 128: uint2 (4 halves) per lane
        int j = s;
        for (; j + 1 < e; j += 2) {
            const uint2* r0 = (const uint2*)(h + (size_t)g_col[j] * ldh);
            const uint2* r1 = (const uint2*)(h + (size_t)g_col[j + 1] * ldh);
            uint2 a = r0[lane], b = r1[lane];
            m0 = __hmax2(m0, __hmax2(*(__half2*)&a.x, *(__half2*)&b.x));
            m1 = __hmax2(m1, __hmax2(*(__half2*)&a.y, *(__half2*)&b.y));
        }
        if (j < e) {
            uint2 a = ((const uint2*)(h + (size_t)g_col[j] * ldh))[lane];
            m0 = __hmax2(m0, *(__half2*)&a.x);
            m1 = __hmax2(m1, *(__half2*)&a.y);
        }
        if (e == s) { unsigned z = 0; m0 = *(__half2*)&z; m1 = m0; }
        uint2 o;
        o.x = *(unsigned*)&m0; o.y = *(unsigned*)&m1;
        ((uint2*)(out + (size_t)w * ldo))[lane] = o;
    }
}

// ------------------------------------------------------ weight pre-convert
// dst layout [n=256][K] fp16; k < K0 from W0[k][n], else W1[k-K0][n]
__global__ void k_wconv(const float* __restrict__ W0, int K0,
                        const float* __restrict__ W1, int K2,
                        unsigned short* __restrict__ dh) {
    int K = K0 + K2;
    int idx = blockIdx.x * 256 + threadIdx.x;
    if (idx >= 256 * K) return;
    int n = idx / K, k = idx - n * K;
    float f = (k < K0) ? W0[(size_t)k * 256 + n] : W1[(size_t)(k - K0) * 256 + n];
    dh[idx] = __half_as_ushort(__float2half_rn(f));
}

// ------------------------------------------------------- mma.sync fp16 GEMM
// C16[M,256] = [A1 | A2] @ W + bias (optional relu); all operands fp16,
// fp32 accumulate, output rounded to fp16.
// CTA 128x128, 8 warps 64x32, K-chunk 64, ldmatrix, THREE-stage cp.async ring.
#define BSTR 72                 // smem halves per row (64 data + 8 pad)
#define STG_H (128 * BSTR)      // halves per array (9216)
#define STG_B (2 * STG_H * 2)   // bytes per stage: A, B (36864)
#define GEMM_SMEM (3 * STG_B)   // 110592

__device__ __forceinline__ unsigned smem_u32(const void* p) {
    unsigned a;
    asm("{ .reg .u64 t; cvta.to.shared.u64 t, %1; cvt.u32.u64 %0, t; }"
        : "=r"(a) : "l"(p));
    return a;
}
__device__ __forceinline__ unsigned pack_f16(float f0, float f1) {
    unsigned short h0 = __half_as_ushort(__float2half_rn(f0));
    unsigned short h1 = __half_as_ushort(__float2half_rn(f1));
    return (unsigned)h0 | ((unsigned)h1 << 16);
}
__device__ __forceinline__ void ldsm_x4(unsigned& r0, unsigned& r1,
                                        unsigned& r2, unsigned& r3, unsigned a) {
    asm volatile("ldmatrix.sync.aligned.m8n8.x4.shared.b16 {%0,%1,%2,%3}, [%4];"
                 : "=r"(r0), "=r"(r1), "=r"(r2), "=r"(r3) : "r"(a));
}
__device__ __forceinline__ void ldsm_x2(unsigned& r0, unsigned& r1, unsigned a) {
    asm volatile("ldmatrix.sync.aligned.m8n8.x2.shared.b16 {%0,%1}, [%2];"
                 : "=r"(r0), "=r"(r1) : "r"(a));
}
__device__ __forceinline__ void cp16(unsigned dst, const void* src) {
    asm volatile("cp.async.cg.shared.global [%0], [%1], 16;"
                 :: "r"(dst), "l"(src));
}
#define MMA_F16(c, a0, a1, a2, a3, b0, b1)                                    \
    asm volatile(                                                             \
        "mma.sync.aligned.m16n8k16.row.col.f32.f16.f16.f32 "                  \
        "{%0,%1,%2,%3}, {%4,%5,%6,%7}, {%8,%9}, {%0,%1,%2,%3};"               \
        : "+f"((c)[0]), "+f"((c)[1]), "+f"((c)[2]), "+f"((c)[3])              \
        : "r"(a0), "r"(a1), "r"(a2), "r"(a3), "r"(b0), "r"(b1))

__global__ __launch_bounds__(256, 2)
void k_gemm_mma(const unsigned short* __restrict__ A1, int lda1, int K0,
                const unsigned short* __restrict__ A2, int lda2, int K2,
                const unsigned short* __restrict__ Wh,
                const float* __restrict__ bias,
                unsigned short* __restrict__ C, int ldc, int M, int doRelu) {
    extern __shared__ __align__(16) unsigned short sm[];

    const int tid = threadIdx.x;
    const int wid = tid >> 5, lane = tid & 31;
    const int lr = lane >> 2, lc = lane & 3;
    const int m0 = blockIdx.x * 128, n0 = blockIdx.y * 128;
    const int wm = (wid >> 2) * 64, wn = (wid & 3) * 32;
    const int K = K0 + K2;
    const int nc = K >> 6;

    const unsigned sbase = smem_u32(sm);
    const unsigned offA = ((lane & 15) * BSTR + ((lane >> 4) << 3)) * 2;
    const unsigned offB = ((lane & 7) * BSTR + (((lane >> 3) & 1) << 3)) * 2;

    float acc[4][4][4];
#pragma unroll
    for (int i = 0; i < 4; i++)
#pragma unroll
        for (int j = 0; j < 4; j++)
#pragma unroll
            for (int q = 0; q < 4; q++) acc[i][j][q] = 0.f;

    const int s_ar = tid >> 1;            // 0..127 (row for A and B staging)
    const int s_ap = (tid & 1) << 5;      // 0 or 32 halves

    // clamped A row (rows >= M load valid data whose outputs are discarded)
    int am = m0 + s_ar; if (am >= M) am = M - 1;

    auto loadAB = [&](int t, int buf) {
        int kb = t << 6;
        const unsigned short* Asel;
        int lda, kloc;
        if (kb < K0) { Asel = A1; lda = lda1; kloc = kb; }
        else         { Asel = A2; lda = lda2; kloc = kb - K0; }
        unsigned ad = sbase + buf * STG_B + (s_ar * BSTR + s_ap) * 2;
        const unsigned short* asrc = Asel + (size_t)am * lda + kloc + s_ap;
        cp16(ad, asrc);       cp16(ad + 16, asrc + 8);
        cp16(ad + 32, asrc + 16); cp16(ad + 48, asrc + 24);
        unsigned bd = sbase + buf * STG_B + 2u * STG_H + (s_ar * BSTR + s_ap) * 2;
        const unsigned short* bsrc = Wh + (size_t)(n0 + s_ar) * K + kb + s_ap;
        cp16(bd, bsrc);       cp16(bd + 16, bsrc + 8);
        cp16(bd + 32, bsrc + 16); cp16(bd + 48, bsrc + 24);
        asm volatile("cp.async.commit_group;");
    };
    auto compute = [&](int buf) {
        unsigned baseA = sbase + buf * STG_B;
        unsigned baseB = baseA + STG_H * 2;
#pragma unroll
        for (int ks = 0; ks < 64; ks += 16) {
            unsigned ah[4][4];
#pragma unroll
            for (int i = 0; i < 4; i++) {
                unsigned ad = (wm + i * 16) * BSTR * 2 + ks * 2 + offA;
                ldsm_x4(ah[i][0], ah[i][1], ah[i][2], ah[i][3], baseA + ad);
            }
#pragma unroll
            for (int j = 0; j < 4; j++) {
                unsigned bd = (wn + j * 8) * BSTR * 2 + ks * 2 + offB;
                unsigned bh0, bh1;
                ldsm_x2(bh0, bh1, baseB + bd);
#pragma unroll
                for (int i = 0; i < 4; i++) {
                    MMA_F16(acc[i][j], ah[i][0], ah[i][1], ah[i][2], ah[i][3], bh0, bh1);
                }
            }
        }
    };

    // prologue: fill 2 of 3 ring slots
    loadAB(0, 0);
    if (nc > 1) loadAB(1, 1);

    int buf = 0;
    for (int t = 0; t < nc; t++) {
        if (t + 1 < nc) asm volatile("cp.async.wait_group 1;");
        else            asm volatile("cp.async.wait_group 0;");
        __syncthreads();
        compute(buf);
        if (t + 2 < nc) {
            int nb_ = buf + 2; if (nb_ >= 3) nb_ -= 3;
            loadAB(t + 2, nb_);
        }
        buf = (buf + 1 == 3) ? 0 : buf + 1;
    }

    // epilogue: fp32 bias/relu, round to fp16, 32-bit stores
#pragma unroll
    for (int i = 0; i < 4; i++) {
        int row0 = m0 + wm + i * 16 + lr;
#pragma unroll
        for (int j = 0; j < 4; j++) {
            int col = n0 + wn + j * 8 + lc * 2;
            float b0 = bias[col], b1 = bias[col + 1];
            float v00 = acc[i][j][0] + b0, v01 = acc[i][j][1] + b1;
            float v10 = acc[i][j][2] + b0, v11 = acc[i][j][3] + b1;
            if (doRelu) {
                v00 = fmaxf(v00, 0.f); v01 = fmaxf(v01, 0.f);
                v10 = fmaxf(v10, 0.f); v11 = fmaxf(v11, 0.f);
            }
            if (row0 < M)
                *(unsigned*)(C + (size_t)row0 * ldc + col) = pack_f16(v00, v01);
            if (row0 + 8 < M)
                *(unsigned*)(C + (size_t)(row0 + 8) * ldc + col) = pack_f16(v10, v11);
        }
    }
}

// -------------------------------------------------------------------- pool
__global__ void k_pool() {
    int b = blockIdx.x;
    int f = blockIdx.y * 256 + threadIdx.x;
    int s = g_gptr[b], e = g_gptr[b + 1];
    const unsigned short* hc = g_hc16;
    float m = -FLT_MAX;
    int n = s;
    for (; n + 3 < e; n += 4) {
        float v0 = __half2float(__ushort_as_half(hc[(size_t)(n + 0) * 1024 + f]));
        float v1 = __half2float(__ushort_as_half(hc[(size_t)(n + 1) * 1024 + f]));
        float v2 = __half2float(__ushort_as_half(hc[(size_t)(n + 2) * 1024 + f]));
        float v3 = __half2float(__ushort_as_half(hc[(size_t)(n + 3) * 1024 + f]));
        m = fmaxf(m, fmaxf(fmaxf(v0, v1), fmaxf(v2, v3)));
    }
    for (; n < e; n++)
        m = fmaxf(m, __half2float(__ushort_as_half(hc[(size_t)n * 1024 + f])));
    g_pool[b * 1024 + f] = (e > s) ? m : 0.f;
}

// -------------------------------------------------------------------- head
__global__ void k_head(const float* __restrict__ W1, const float* __restrict__ b1,
                       const float* __restrict__ W2, const float* __restrict__ b2,
                       float* __restrict__ outbuf, int G, int DT) {
    __shared__ float sg[1024];
    __shared__ float sl[256];
    __shared__ float so[32];
    __shared__ float slse;
    int b = blockIdx.x, t = threadIdx.x;
    for (int k = t; k < 1024; k += 256) sg[k] = g_pool[b * 1024 + k];
    __syncthreads();
    float acc = b1[t];
#pragma unroll 4
    for (int k = 0; k < 1024; k++) acc = fmaf(sg[k], W1[k * 256 + t], acc);
    acc = fmaxf(acc, 0.f);
    sl[t] = acc;
    outbuf[2 * G * DT + b * 256 + t] = acc;
    __syncthreads();
    if (t < DT) {
        float o = b2[t];
        for (int k = 0; k < 256; k++) o = fmaf(sl[k], W2[k * DT + t], o);
        so[t] = o;
    }
    __syncthreads();
    if (t == 0) {
        float mx = -FLT_MAX;
        for (int j = 0; j < DT; j++) mx = fmaxf(mx, so[j]);
        float s2 = 0.f;
        for (int j = 0; j < DT; j++) s2 += expf(so[j] - mx);
        slse = mx + logf(s2);
    }
    __syncthreads();
    if (t < DT) {
        outbuf[b * DT + t] = so[t] - slse;
        outbuf[G * DT + b * DT + t] = so[t];
    }
}

// ------------------------------------------------------------------ launch
extern "C" void kernel_launch(void* const* d_in, const int* in_sizes, int n_in,
                              void* d_out, int out_size) {
    const float* x = (const float*)d_in[0];
    const int* ei = (const int*)d_in[1];
    const int* batch = (const int*)d_in[2];
    const float *Wl[4], *bl[4], *Wr[4], *Wm[4], *bm[4];
    int p = 3;
    for (int l = 0; l < 4; l++) {
        Wl[l] = (const float*)d_in[p++];
        bl[l] = (const float*)d_in[p++];
        Wr[l] = (const float*)d_in[p++];
        Wm[l] = (const float*)d_in[p++];
        bm[l] = (const float*)d_in[p++];
    }
    const float* fc1W = (const float*)d_in[p++];
    const float* fc1b = (const float*)d_in[p++];
    const float* fc2W = (const float*)d_in[p++];
    const float* fc2b = (const float*)d_in[p++];

    int N = in_sizes[0] / 128;
    int E = in_sizes[1] / 2;
    int DT = in_sizes[26];
    int G = out_size / (2 * DT + DE);
    int Mb = (N + 127) / 128;

    int *deg, *rowptr, *cursor, *gcnt, *gptr;
    cudaGetSymbolAddress((void**)&deg, g_deg);
    cudaGetSymbolAddress((void**)&rowptr, g_rowptr);
    cudaGetSymbolAddress((void**)&cursor, g_cursor);
    cudaGetSymbolAddress((void**)&gcnt, g_gcnt);
    cudaGetSymbolAddress((void**)&gptr, g_gptr);
    void *px16, *pagg, *ptmp, *phc, *pW1h, *pW2h;
    cudaGetSymbolAddress(&px16, g_x16);
    cudaGetSymbolAddress(&pagg, g_agg16);
    cudaGetSymbolAddress(&ptmp, g_tmp16);
    cudaGetSymbolAddress(&phc, g_hc16);
    cudaGetSymbolAddress(&pW1h, g_W1h);
    cudaGetSymbolAddress(&pW2h, g_W2h);
    unsigned short* x16 = (unsigned short*)px16;
    unsigned short* agg16 = (unsigned short*)pagg;
    unsigned short* tmp16 = (unsigned short*)ptmp;
    unsigned short* hc16 = (unsigned short*)phc;

    cudaFuncSetAttribute(k_gemm_mma,
                         cudaFuncAttributeMaxDynamicSharedMemorySize, GEMM_SMEM);

    int mx = (N > G) ? N : G;
    k_zero<<<(mx + 255) / 256, 256>>>(N, G);
    k_hist_edges<<<(E + 255) / 256, 256>>>(ei, E, N);
    k_hist_nodes<<<(N + 255) / 256, 256>>>(batch, N, G);
    int nb = (N + 255) / 256;
    k_scan_blk<<<nb, 256>>>(deg, rowptr, N);
    k_scan_top<<<1, 256>>>(nb, rowptr, cursor, N);
    k_scan_add<<<nb, 256>>>(rowptr, cursor, N);
    k_scan<<<1, 1024>>>(gcnt, gptr, gptr, G);
    k_scatter<<<(E + 255) / 256, 256>>>(ei, E, N);
    k_x16<<<(N * 128 + 255) / 256, 256>>>(x, N * 128);

    for (int l = 0; l < 4; l++) {
        int din = l ? 256 : 128;
        int K1 = 2 * din;
        unsigned short* w1h = (unsigned short*)pW1h + (size_t)l * 256 * 512;
        unsigned short* w2h = (unsigned short*)pW2h + (size_t)l * 256 * 256;
        k_wconv<<<(256 * K1 + 255) / 256, 256>>>(Wl[l], din, Wr[l], din, w1h);
        k_wconv<<<(256 * 256 + 255) / 256, 256>>>(Wm[l], 256, nullptr, 0, w2h);
    }

    for (int l = 0; l < 4; l++) {
        const unsigned short* h = l ? (hc16 + (l - 1) * DE) : x16;
        int ldh = l ? 1024 : 128;
        int din = l ? 256 : 128;
        unsigned short* w1h = (unsigned short*)pW1h + (size_t)l * 256 * 512;
        unsigned short* w2h = (unsigned short*)pW2h + (size_t)l * 256 * 256;
        k_agg16<<<(N * 32 + 255) / 256, 256>>>(h, ldh, din, agg16, din, N);
        dim3 gg(Mb, 2);
        k_gemm_mma<<<gg, 256, GEMM_SMEM>>>(agg16, din, din, h, ldh, din,
                                           w1h, bl[l], tmp16, 256, N, 0);
        k_gemm_mma<<<gg, 256, GEMM_SMEM>>>(tmp16, 256, 256, nullptr, 0, 0,
                                           w2h, bm[l], hc16 + l * DE, 1024, N, 1);
    }
    k_pool<<<dim3(G, 4), 256>>>();
    k_head<<<G, 256>>>(fc1W, fc1b, fc2W, fc2b, (float*)d_out, G, DT);
}